// round 13
// baseline (speedup 1.0000x reference)
#include <cuda_runtime.h>
#include <cuda_fp16.h>
#include <cstdint>

// ---------------------------------------------------------------------------
// HOP interaction layer:
//   k0 : seg table + one-time transpose-pack of W (-> g_WtF) and selfW.
//        Kills the 32-way STS bank-conflict fill that made k1 29us.
//   k1 : G[j,o,d] (fp16) = sum_f feat[j,f]*W[d,o,f]  — W read via coalesced
//        LDG.64 from pre-transposed global (L1-resident), no smem at all.
//        + self[a,o] = feat[a] @ selfW^T + b
//   k2a: h[p,o] = sum_d sense(p,d) * G[j_p,o,d]   (warp per pair, fp16 G)
//   k2b: tf[a,c,o]= sum_p rhat[p,c]*h[p,o] + invariants + GN + mixing + self
// ---------------------------------------------------------------------------

#define HARD_CUTOFF 6.5f
#define GN_EPS 1e-5f
#define PI_OVER_13 0.2416609733530618f  // 0.5*pi/6.5

typedef unsigned long long ull;

__device__ __half g_Gh[8192 * 512];               // 8 MB  [atom][o][d] fp16
__device__ float g_H[81920 * 32];                 // 10 MB
__device__ float g_self[8192 * 32];               // 1 MB
__device__ int g_seg[8192 + 1];
__device__ __align__(16) float g_WtF[16384];      // W packed [f][q][o][e]
__device__ float g_sWt[1024];                     // selfW^T [f][o]

__device__ __forceinline__ ull pack2(float lo, float hi) {
    ull r;
    asm("mov.b64 %0, {%1, %2};" : "=l"(r) : "f"(lo), "f"(hi));
    return r;
}
__device__ __forceinline__ void unpack2(ull v, float& lo, float& hi) {
    asm("mov.b64 {%0, %1}, %2;" : "=f"(lo), "=f"(hi) : "l"(v));
}
__device__ __forceinline__ ull ffma2(ull a, ull b, ull c) {
    ull d;
    asm("fma.rn.f32x2 %0, %1, %2, %3;" : "=l"(d) : "l"(a), "l"(b), "l"(c));
    return d;
}

// ---- k0: seg table + W / selfW transpose --------------------------------
__global__ void k0_prep(const int* __restrict__ pf,
                        const float* __restrict__ W,      // [d][o][f]
                        const float* __restrict__ selfW,  // [o][f]
                        int n_pairs, int n_atoms) {
    int bid = blockIdx.x;
    if (bid < 64) {
        // W transpose-pack: out io = f*512 + q*64 + o*2 + e  (d = 2q+e)
        int io = bid * 256 + threadIdx.x;
        int f = io >> 9;
        int t = io & 511;
        int q = t >> 6;
        int u = t & 63;
        int o = u >> 1;
        int e = u & 1;
        int d = q * 2 + e;
        g_WtF[io] = W[d * 1024 + o * 32 + f];
        return;
    }
    if (bid == 64) {
        for (int k = threadIdx.x; k < 1024; k += blockDim.x)
            g_sWt[(k & 31) * 32 + (k >> 5)] = selfW[k];  // [f][o]
        return;
    }
    int p = (bid - 65) * blockDim.x + threadIdx.x;
    if (p > n_pairs) return;
    int cur  = (p < n_pairs) ? pf[p] : n_atoms;
    int prev = (p == 0) ? -1 : pf[p - 1];
    if (cur > n_atoms) cur = n_atoms;
    if (prev > n_atoms) prev = n_atoms;
    for (int a = prev + 1; a <= cur; ++a) g_seg[a] = p;
}

// ---- k1: G (fp16) + self precompute — no shared memory ------------------
__global__ void k1_precompute_G(const float* __restrict__ feat,
                                const float* __restrict__ selfB,  // [32]
                                int n_atoms) {
    const ull* __restrict__ Wt = (const ull*)g_WtF;  // idx: f*256 + q*32 + o

    const int lane = threadIdx.x & 31;
    const int warp = threadIdx.x >> 5;
    const int warps_per_blk = blockDim.x >> 5;
    const int nwarps = warps_per_blk * gridDim.x;
    const int gw = blockIdx.x * warps_per_blk + warp;

    for (int a0 = gw * 4; a0 < n_atoms; a0 += nwarps * 4) {
        float fv[4];
#pragma unroll
        for (int k = 0; k < 4; k++)
            fv[k] = (a0 + k < n_atoms) ? feat[(a0 + k) * 32 + lane] : 0.0f;

        ull acc[4][8];
        float sp[4];
        float sb = __ldg(selfB + lane);
#pragma unroll
        for (int k = 0; k < 4; k++) {
            sp[k] = sb;
#pragma unroll
            for (int q = 0; q < 8; q++) acc[k][q] = pack2(0.f, 0.f);
        }

#pragma unroll
        for (int f = 0; f < 32; f++) {
            ull w[8];
#pragma unroll
            for (int q = 0; q < 8; q++) w[q] = Wt[f * 256 + q * 32 + lane];
            float swt = g_sWt[f * 32 + lane];
#pragma unroll
            for (int k = 0; k < 4; k++) {
                float b = __shfl_sync(0xffffffffu, fv[k], f);
                ull b2 = pack2(b, b);
#pragma unroll
                for (int q = 0; q < 8; q++) acc[k][q] = ffma2(b2, w[q], acc[k][q]);
                sp[k] = fmaf(b, swt, sp[k]);
            }
        }

#pragma unroll
        for (int k = 0; k < 4; k++) {
            int a = a0 + k;
            if (a < n_atoms) {
                uint4 u[2];
                unsigned* uu = (unsigned*)u;
#pragma unroll
                for (int q = 0; q < 8; q++) {
                    float x0, x1;
                    unpack2(acc[k][q], x0, x1);
                    __half2 h2 = __floats2half2_rn(x0, x1);
                    uu[q] = *(unsigned*)&h2;
                }
                uint4* dst = (uint4*)(g_Gh + (size_t)a * 512 + lane * 16);
                dst[0] = u[0];
                dst[1] = u[1];
                g_self[a * 32 + lane] = sp[k];
            }
        }
    }
}

// ---- k2a: warp per pair -> h[p, o], fp16 G ------------------------------
__global__ void k2a_pairs(const float* __restrict__ dist,    // [P]
                          const float* __restrict__ mu,      // [16]
                          const float* __restrict__ sigma,   // [16]
                          const int* __restrict__ ps,        // [P]
                          int n_pairs) {
    const int p = blockIdx.x * (blockDim.x >> 5) + (threadIdx.x >> 5);
    if (p >= n_pairs) return;
    const int lane = threadIdx.x & 31;

    const int j = __ldg(ps + p);
    const float d = __ldg(dist + p);

    const uint4* Gp = (const uint4*)(g_Gh + (size_t)j * 512 + lane * 16);
    uint4 u0 = __ldg(Gp + 0), u1 = __ldg(Gp + 1);

    const float mu_l = __ldg(mu + (lane & 15));
    const float inv_sg = __fdividef(1.0f, __ldg(sigma + (lane & 15)));
    float invd = __fdividef(1.0f, d);
    float z = (invd - mu_l) * inv_sg;
    float cc = __cosf(PI_OVER_13 * d);
    float cut = (d < HARD_CUTOFF) ? cc * cc : 0.0f;
    float s = __expf(-0.5f * z * z) * cut;   // per-lane, d = lane&15

    unsigned ua[8] = {u0.x, u0.y, u0.z, u0.w, u1.x, u1.y, u1.z, u1.w};

    float hA = 0.f, hB = 0.f, hC = 0.f, hD = 0.f;
#pragma unroll
    for (int q = 0; q < 8; q++) {
        __half2 h2 = *(__half2*)&ua[q];
        float2 g2 = __half22float2(h2);
        float s0 = __shfl_sync(0xffffffffu, s, 2 * q);
        float s1 = __shfl_sync(0xffffffffu, s, 2 * q + 1);
        if (q < 2)      { hA = fmaf(s0, g2.x, hA); hA = fmaf(s1, g2.y, hA); }
        else if (q < 4) { hB = fmaf(s0, g2.x, hB); hB = fmaf(s1, g2.y, hB); }
        else if (q < 6) { hC = fmaf(s0, g2.x, hC); hC = fmaf(s1, g2.y, hC); }
        else            { hD = fmaf(s0, g2.x, hD); hD = fmaf(s1, g2.y, hD); }
    }

    g_H[(size_t)p * 32 + lane] = (hA + hB) + (hC + hD);
}

__device__ __forceinline__ float warp_sum(float v) {
#pragma unroll
    for (int o = 16; o > 0; o >>= 1) v += __shfl_xor_sync(0xffffffffu, v, o);
    return v;
}

// ---- k2b: warp per atom, contiguous h gather + epilogue -----------------
__global__ void k2b_atoms(const float* __restrict__ rhats,   // [P][4]
                          const float* __restrict__ Mw,      // [64][32]
                          const float* __restrict__ gnw,     // [64]
                          const float* __restrict__ gnb,     // [64]
                          float* __restrict__ out,           // [N][32]
                          int n_atoms) {
    const int a = blockIdx.x * (blockDim.x >> 5) + (threadIdx.x >> 5);
    if (a >= n_atoms) return;
    const int lane = threadIdx.x & 31;

    const int pstart = g_seg[a];
    const int pend = g_seg[a + 1];

    float tf0 = 0.f, tf1 = 0.f, tf2 = 0.f, tf3 = 0.f;

#pragma unroll 4
    for (int p = pstart; p < pend; ++p) {
        float h = __ldg(g_H + (size_t)p * 32 + lane);
        float4 r = *(const float4*)(rhats + 4 * p);
        tf0 = fmaf(r.x, h, tf0);
        tf1 = fmaf(r.y, h, tf1);
        tf2 = fmaf(r.z, h, tf2);
        tf3 = fmaf(r.w, h, tf3);
    }

    float i0 = tf0;
    float i1 = tf1 * tf1 + tf2 * tf2 + tf3 * tf3;

    float m0 = warp_sum(i0) * (1.0f / 32.0f);
    float m1 = warp_sum(i1) * (1.0f / 32.0f);
    float d0 = i0 - m0, d1 = i1 - m1;
    float v0 = warp_sum(d0 * d0) * (1.0f / 32.0f);
    float v1 = warp_sum(d1 * d1) * (1.0f / 32.0f);
    float x0 = d0 * rsqrtf(v0 + GN_EPS) * __ldg(gnw + lane) + __ldg(gnb + lane);
    float x1 = d1 * rsqrtf(v1 + GN_EPS) * __ldg(gnw + 32 + lane) + __ldg(gnb + 32 + lane);

    float mixA = 0.f, mixB = 0.f;
#pragma unroll
    for (int o = 0; o < 32; o++) {
        float a0 = __shfl_sync(0xffffffffu, x0, o);
        float a1 = __shfl_sync(0xffffffffu, x1, o);
        mixA = fmaf(a0, __ldg(Mw + (o * 2 + 0) * 32 + lane), mixA);
        mixB = fmaf(a1, __ldg(Mw + (o * 2 + 1) * 32 + lane), mixB);
    }

    out[a * 32 + lane] = (mixA + mixB) + g_self[a * 32 + lane];
}

extern "C" void kernel_launch(void* const* d_in, const int* in_sizes, int n_in,
                              void* d_out, int out_size) {
    const float* in_features = (const float*)d_in[0];
    const float* tensor_rhats = (const float*)d_in[1];
    const float* dist_pairs = (const float*)d_in[2];
    const float* int_weights = (const float*)d_in[3];
    const float* selfint_w = (const float*)d_in[4];
    const float* selfint_b = (const float*)d_in[5];
    const float* mixing_weights = (const float*)d_in[6];
    const float* gn_weight = (const float*)d_in[7];
    const float* gn_bias = (const float*)d_in[8];
    const float* sens_mu = (const float*)d_in[9];
    const float* sens_sigma = (const float*)d_in[10];
    const int* pair_first = (const int*)d_in[11];
    const int* pair_second = (const int*)d_in[12];
    float* out = (float*)d_out;

    int n_atoms = in_sizes[0] / 32;
    int n_pairs = in_sizes[2];

    // k0: seg table (blocks 65..) + W transpose (0..63) + selfW (64)
    int seg_blocks = (n_pairs + 256) / 256;
    k0_prep<<<65 + seg_blocks, 256>>>(pair_first, int_weights, selfint_w,
                                      n_pairs, n_atoms);

    // k1: G + self precompute (no smem)
    int k1_blocks = (n_atoms + 31) / 32;
    k1_precompute_G<<<k1_blocks, 256>>>(in_features, selfint_b, n_atoms);

    // k2a: warp per pair -> h
    int k2a_blocks = (n_pairs + 7) / 8;
    k2a_pairs<<<k2a_blocks, 256>>>(dist_pairs, sens_mu, sens_sigma,
                                   pair_second, n_pairs);

    // k2b: warp per atom -> out
    int k2b_blocks = (n_atoms + 7) / 8;
    k2b_atoms<<<k2b_blocks, 256>>>(tensor_rhats, mixing_weights,
                                   gn_weight, gn_bias, out, n_atoms);
}

// round 15
// speedup vs baseline: 1.5161x; 1.5161x over previous
#include <cuda_runtime.h>
#include <cuda_fp16.h>
#include <cstdint>

// ---------------------------------------------------------------------------
// HOP interaction layer:
//   k0 : seg table + ONE-TIME transpose-pack of W into g_WtF (final smem
//        layout) and selfW^T. This moves the 32-way-conflict scatter out of
//        the per-block path.
//   k1 : G[j,o,d] (fp16) = sum_f feat[j,f]*W[d,o,f]  (f32x2 smem GEMM; smem
//        filled by straight float4 memcpy of g_WtF -> conflict-free)
//        + self[a,o] = feat[a] @ selfW^T + b
//   k2a: h[p,o] = sum_d sense(p,d) * G[j_p,o,d]   (warp per pair, fp16 G)
//   k2b: tf[a,c,o]= sum_p rhat[p,c]*h[p,o] + invariants + GN + mixing + self
// ---------------------------------------------------------------------------

#define HARD_CUTOFF 6.5f
#define GN_EPS 1e-5f
#define PI_OVER_13 0.2416609733530618f  // 0.5*pi/6.5

typedef unsigned long long ull;

__device__ __half g_Gh[8192 * 512];               // 8 MB  [atom][o][d] fp16
__device__ float g_H[81920 * 32];                 // 10 MB
__device__ float g_self[8192 * 32];               // 1 MB
__device__ int g_seg[8192 + 1];
__device__ __align__(16) float g_WtF[16384];      // W packed [f][q][o][e]
__device__ __align__(16) float g_sWt[1024];       // selfW^T [f][o]

__device__ __forceinline__ ull pack2(float lo, float hi) {
    ull r;
    asm("mov.b64 %0, {%1, %2};" : "=l"(r) : "f"(lo), "f"(hi));
    return r;
}
__device__ __forceinline__ void unpack2(ull v, float& lo, float& hi) {
    asm("mov.b64 {%0, %1}, %2;" : "=f"(lo), "=f"(hi) : "l"(v));
}
__device__ __forceinline__ ull ffma2(ull a, ull b, ull c) {
    ull d;
    asm("fma.rn.f32x2 %0, %1, %2, %3;" : "=l"(d) : "l"(a), "l"(b), "l"(c));
    return d;
}

// ---- k0: seg table + one-time W / selfW transpose -----------------------
__global__ void k0_prep(const int* __restrict__ pf,
                        const float* __restrict__ W,      // [d][o][f]
                        const float* __restrict__ selfW,  // [o][f]
                        int n_pairs, int n_atoms) {
    int bid = blockIdx.x;
    if (bid < 64) {
        // consecutive OUTPUT index (coalesced STG); scattered LDG is fine once
        int io = bid * 256 + threadIdx.x;       // io = f*512 + q*64 + o*2 + e
        int f = io >> 9;
        int t = io & 511;
        int q = t >> 6;
        int u = t & 63;
        int o = u >> 1;
        int e = u & 1;
        int d = q * 2 + e;
        g_WtF[io] = W[d * 1024 + o * 32 + f];
        return;
    }
    if (bid == 64) {
        for (int k = threadIdx.x; k < 1024; k += blockDim.x)
            g_sWt[(k & 31) * 32 + (k >> 5)] = selfW[k];   // [f][o]
        return;
    }
    int p = (bid - 65) * blockDim.x + threadIdx.x;
    if (p > n_pairs) return;
    int cur  = (p < n_pairs) ? pf[p] : n_atoms;
    int prev = (p == 0) ? -1 : pf[p - 1];
    if (cur > n_atoms) cur = n_atoms;
    if (prev > n_atoms) prev = n_atoms;
    for (int a = prev + 1; a <= cur; ++a) g_seg[a] = p;
}

// ---- k1: G (fp16) + self precompute; conflict-free smem staging ---------
// dynamic smem floats: [0,16384) Ws packed; [16384,17408) sWt; [17408,17440) sB
__global__ void k1_precompute_G(const float* __restrict__ feat,
                                const float* __restrict__ selfB,  // [32]
                                int n_atoms) {
    extern __shared__ float Ws[];
    float* sWt = Ws + 16384;
    float* sB  = Ws + 16384 + 1024;
    // straight float4 memcpy: coalesced LDG.128 + consecutive STS.128
    {
        const float4* src = (const float4*)g_WtF;
        float4* dst = (float4*)Ws;
        for (int i = threadIdx.x; i < 4096; i += blockDim.x) dst[i] = src[i];
        const float4* src2 = (const float4*)g_sWt;
        float4* dst2 = (float4*)sWt;
        for (int i = threadIdx.x; i < 256; i += blockDim.x) dst2[i] = src2[i];
        if (threadIdx.x < 32) sB[threadIdx.x] = selfB[threadIdx.x];
    }
    __syncthreads();
    const ull* S2 = (const ull*)Ws;  // idx: f*256 + q*32 + o  (q = d/2)

    const int lane = threadIdx.x & 31;
    const int warp = threadIdx.x >> 5;
    const int warps_per_blk = blockDim.x >> 5;
    const int nwarps = warps_per_blk * gridDim.x;
    const int gw = blockIdx.x * warps_per_blk + warp;

    for (int a0 = gw * 4; a0 < n_atoms; a0 += nwarps * 4) {
        float fv[4];
#pragma unroll
        for (int k = 0; k < 4; k++)
            fv[k] = (a0 + k < n_atoms) ? feat[(a0 + k) * 32 + lane] : 0.0f;

        ull acc[4][8];
        float sp[4];
#pragma unroll
        for (int k = 0; k < 4; k++) {
            sp[k] = sB[lane];
#pragma unroll
            for (int q = 0; q < 8; q++) acc[k][q] = pack2(0.f, 0.f);
        }

#pragma unroll
        for (int f = 0; f < 32; f++) {
            ull w[8];
#pragma unroll
            for (int q = 0; q < 8; q++) w[q] = S2[f * 256 + q * 32 + lane];
            float swt = sWt[f * 32 + lane];
#pragma unroll
            for (int k = 0; k < 4; k++) {
                float b = __shfl_sync(0xffffffffu, fv[k], f);
                ull b2 = pack2(b, b);
#pragma unroll
                for (int q = 0; q < 8; q++) acc[k][q] = ffma2(b2, w[q], acc[k][q]);
                sp[k] = fmaf(b, swt, sp[k]);
            }
        }

#pragma unroll
        for (int k = 0; k < 4; k++) {
            int a = a0 + k;
            if (a < n_atoms) {
                uint4 u[2];
                unsigned* uu = (unsigned*)u;
#pragma unroll
                for (int q = 0; q < 8; q++) {
                    float x0, x1;
                    unpack2(acc[k][q], x0, x1);
                    __half2 h2 = __floats2half2_rn(x0, x1);
                    uu[q] = *(unsigned*)&h2;
                }
                uint4* dst = (uint4*)(g_Gh + (size_t)a * 512 + lane * 16);
                dst[0] = u[0];
                dst[1] = u[1];
                g_self[a * 32 + lane] = sp[k];
            }
        }
    }
}

// ---- k2a: warp per pair -> h[p, o], fp16 G ------------------------------
__global__ void k2a_pairs(const float* __restrict__ dist,    // [P]
                          const float* __restrict__ mu,      // [16]
                          const float* __restrict__ sigma,   // [16]
                          const int* __restrict__ ps,        // [P]
                          int n_pairs) {
    const int p = blockIdx.x * (blockDim.x >> 5) + (threadIdx.x >> 5);
    if (p >= n_pairs) return;
    const int lane = threadIdx.x & 31;

    const int j = __ldg(ps + p);
    const float d = __ldg(dist + p);

    const uint4* Gp = (const uint4*)(g_Gh + (size_t)j * 512 + lane * 16);
    uint4 u0 = __ldg(Gp + 0), u1 = __ldg(Gp + 1);

    const float mu_l = __ldg(mu + (lane & 15));
    const float inv_sg = __fdividef(1.0f, __ldg(sigma + (lane & 15)));
    float invd = __fdividef(1.0f, d);
    float z = (invd - mu_l) * inv_sg;
    float cc = __cosf(PI_OVER_13 * d);
    float cut = (d < HARD_CUTOFF) ? cc * cc : 0.0f;
    float s = __expf(-0.5f * z * z) * cut;   // per-lane, d = lane&15

    unsigned ua[8] = {u0.x, u0.y, u0.z, u0.w, u1.x, u1.y, u1.z, u1.w};

    float hA = 0.f, hB = 0.f, hC = 0.f, hD = 0.f;
#pragma unroll
    for (int q = 0; q < 8; q++) {
        __half2 h2 = *(__half2*)&ua[q];
        float2 g2 = __half22float2(h2);
        float s0 = __shfl_sync(0xffffffffu, s, 2 * q);
        float s1 = __shfl_sync(0xffffffffu, s, 2 * q + 1);
        if (q < 2)      { hA = fmaf(s0, g2.x, hA); hA = fmaf(s1, g2.y, hA); }
        else if (q < 4) { hB = fmaf(s0, g2.x, hB); hB = fmaf(s1, g2.y, hB); }
        else if (q < 6) { hC = fmaf(s0, g2.x, hC); hC = fmaf(s1, g2.y, hC); }
        else            { hD = fmaf(s0, g2.x, hD); hD = fmaf(s1, g2.y, hD); }
    }

    g_H[(size_t)p * 32 + lane] = (hA + hB) + (hC + hD);
}

__device__ __forceinline__ float warp_sum(float v) {
#pragma unroll
    for (int o = 16; o > 0; o >>= 1) v += __shfl_xor_sync(0xffffffffu, v, o);
    return v;
}

// ---- k2b: warp per atom, contiguous h gather + epilogue -----------------
__global__ void k2b_atoms(const float* __restrict__ rhats,   // [P][4]
                          const float* __restrict__ Mw,      // [64][32]
                          const float* __restrict__ gnw,     // [64]
                          const float* __restrict__ gnb,     // [64]
                          float* __restrict__ out,           // [N][32]
                          int n_atoms) {
    const int a = blockIdx.x * (blockDim.x >> 5) + (threadIdx.x >> 5);
    if (a >= n_atoms) return;
    const int lane = threadIdx.x & 31;

    const int pstart = g_seg[a];
    const int pend = g_seg[a + 1];

    float tf0 = 0.f, tf1 = 0.f, tf2 = 0.f, tf3 = 0.f;

#pragma unroll 4
    for (int p = pstart; p < pend; ++p) {
        float h = __ldg(g_H + (size_t)p * 32 + lane);
        float4 r = *(const float4*)(rhats + 4 * p);
        tf0 = fmaf(r.x, h, tf0);
        tf1 = fmaf(r.y, h, tf1);
        tf2 = fmaf(r.z, h, tf2);
        tf3 = fmaf(r.w, h, tf3);
    }

    float i0 = tf0;
    float i1 = tf1 * tf1 + tf2 * tf2 + tf3 * tf3;

    float m0 = warp_sum(i0) * (1.0f / 32.0f);
    float m1 = warp_sum(i1) * (1.0f / 32.0f);
    float d0 = i0 - m0, d1 = i1 - m1;
    float v0 = warp_sum(d0 * d0) * (1.0f / 32.0f);
    float v1 = warp_sum(d1 * d1) * (1.0f / 32.0f);
    float x0 = d0 * rsqrtf(v0 + GN_EPS) * __ldg(gnw + lane) + __ldg(gnb + lane);
    float x1 = d1 * rsqrtf(v1 + GN_EPS) * __ldg(gnw + 32 + lane) + __ldg(gnb + 32 + lane);

    float mixA = 0.f, mixB = 0.f;
#pragma unroll
    for (int o = 0; o < 32; o++) {
        float a0 = __shfl_sync(0xffffffffu, x0, o);
        float a1 = __shfl_sync(0xffffffffu, x1, o);
        mixA = fmaf(a0, __ldg(Mw + (o * 2 + 0) * 32 + lane), mixA);
        mixB = fmaf(a1, __ldg(Mw + (o * 2 + 1) * 32 + lane), mixB);
    }

    out[a * 32 + lane] = (mixA + mixB) + g_self[a * 32 + lane];
}

extern "C" void kernel_launch(void* const* d_in, const int* in_sizes, int n_in,
                              void* d_out, int out_size) {
    const float* in_features = (const float*)d_in[0];
    const float* tensor_rhats = (const float*)d_in[1];
    const float* dist_pairs = (const float*)d_in[2];
    const float* int_weights = (const float*)d_in[3];
    const float* selfint_w = (const float*)d_in[4];
    const float* selfint_b = (const float*)d_in[5];
    const float* mixing_weights = (const float*)d_in[6];
    const float* gn_weight = (const float*)d_in[7];
    const float* gn_bias = (const float*)d_in[8];
    const float* sens_mu = (const float*)d_in[9];
    const float* sens_sigma = (const float*)d_in[10];
    const int* pair_first = (const int*)d_in[11];
    const int* pair_second = (const int*)d_in[12];
    float* out = (float*)d_out;

    int n_atoms = in_sizes[0] / 32;
    int n_pairs = in_sizes[2];

    cudaFuncSetAttribute(k1_precompute_G,
                         cudaFuncAttributeMaxDynamicSharedMemorySize, 69760);

    // k0: W transpose (blocks 0..63) + selfW (64) + seg table (65..)
    int seg_blocks = (n_pairs + 256) / 256;
    k0_prep<<<65 + seg_blocks, 256>>>(pair_first, int_weights, selfint_w,
                                      n_pairs, n_atoms);

    // k1: G + self precompute (conflict-free smem staging)
    int k1_blocks = (n_atoms + 31) / 32;
    k1_precompute_G<<<k1_blocks, 256, 69760>>>(in_features, selfint_b, n_atoms);

    // k2a: warp per pair -> h
    int k2a_blocks = (n_pairs + 7) / 8;
    k2a_pairs<<<k2a_blocks, 256>>>(dist_pairs, sens_mu, sens_sigma,
                                   pair_second, n_pairs);

    // k2b: warp per atom -> out
    int k2b_blocks = (n_atoms + 7) / 8;
    k2b_atoms<<<k2b_blocks, 256>>>(tensor_rhats, mixing_weights,
                                   gn_weight, gn_bias, out, n_atoms);
}